// round 7
// baseline (speedup 1.0000x reference)
#include <cuda_runtime.h>
#include <cuda_bf16.h>
#include <cstdint>

#define B_SZ 8192
#define N_SZ 8192
#define D_SZ 1024
#define EPS_F 1e-6f
constexpr float INV_T = 1.0f / 0.92f;

// ---------------- scratch (device globals; no allocations allowed) ----------
__device__ __nv_bfloat16 g_qhat[(size_t)B_SZ * D_SZ]; // 16 MB
__device__ __nv_bfloat16 g_nhat[(size_t)N_SZ * D_SZ]; // 16 MB
__device__ float g_s1[B_SZ];
__device__ float g_S2[B_SZ];
__device__ float g_loss;

// ---------------------------------------------------------------------------
#define CP_ASYNC16(dst, src) \
    asm volatile("cp.async.cg.shared.global [%0], [%1], 16;" :: "r"(dst), "l"(src) : "memory")
#define CP_COMMIT() asm volatile("cp.async.commit_group;" ::: "memory")
#define CP_WAIT1()  asm volatile("cp.async.wait_group 1;" ::: "memory")
#define CP_WAIT0()  asm volatile("cp.async.wait_group 0;" ::: "memory")

__device__ __forceinline__ uint32_t smem_u32(const void* p) {
    uint32_t a;
    asm("{ .reg .u64 t; cvta.to.shared.u64 t, %1; cvt.u32.u64 %0, t; }"
        : "=r"(a) : "l"(p));
    return a;
}
__device__ __forceinline__ void ldsm4(uint32_t* r, uint32_t addr) {
    asm volatile("ldmatrix.sync.aligned.m8n8.x4.shared.b16 {%0,%1,%2,%3}, [%4];"
                 : "=r"(r[0]), "=r"(r[1]), "=r"(r[2]), "=r"(r[3]) : "r"(addr));
}
__device__ __forceinline__ void mma16816(float* d, const uint32_t* a,
                                         uint32_t b0, uint32_t b1) {
    asm volatile(
        "mma.sync.aligned.m16n8k16.row.col.f32.bf16.bf16.f32 "
        "{%0,%1,%2,%3}, {%4,%5,%6,%7}, {%8,%9}, {%0,%1,%2,%3};"
        : "+f"(d[0]), "+f"(d[1]), "+f"(d[2]), "+f"(d[3])
        : "r"(a[0]), "r"(a[1]), "r"(a[2]), "r"(a[3]), "r"(b0), "r"(b1));
}

// ---------------------------------------------------------------------------
// Kernel 1: prep q,p -> qhat (bf16), s1, zero S2
// ---------------------------------------------------------------------------
__global__ __launch_bounds__(256) void prep_qp_kernel(const float* __restrict__ q,
                                                      const float* __restrict__ p) {
    const int b = blockIdx.x;
    const int t = threadIdx.x;
    const float4* q4 = (const float4*)(q + (size_t)b * D_SZ);
    const float4* p4 = (const float4*)(p + (size_t)b * D_SZ);

    float4 a = q4[t];
    float4 c = p4[t];
    float qq = a.x * a.x + a.y * a.y + a.z * a.z + a.w * a.w;
    float pp = c.x * c.x + c.y * c.y + c.z * c.z + c.w * c.w;
    float qp = a.x * c.x + a.y * c.y + a.z * c.z + a.w * c.w;

    #pragma unroll
    for (int off = 16; off > 0; off >>= 1) {
        qq += __shfl_xor_sync(0xffffffff, qq, off);
        pp += __shfl_xor_sync(0xffffffff, pp, off);
        qp += __shfl_xor_sync(0xffffffff, qp, off);
    }
    __shared__ float sq[8], sp[8], sqp[8], s_rq;
    const int wid = t >> 5, lane = t & 31;
    if (lane == 0) { sq[wid] = qq; sp[wid] = pp; sqp[wid] = qp; }
    __syncthreads();
    if (t == 0) {
        float tq = 0.f, tp = 0.f, tqp = 0.f;
        #pragma unroll
        for (int i = 0; i < 8; i++) { tq += sq[i]; tp += sp[i]; tqp += sqp[i]; }
        float qn = sqrtf(tq), pn = sqrtf(tp);
        float pos = tqp / fmaxf(qn * pn, EPS_F);
        g_s1[b] = __expf(pos * INV_T);
        g_S2[b] = 0.0f;
        s_rq = (qn > 0.f) ? (1.0f / qn) : 0.0f;
    }
    __syncthreads();
    const float rq = s_rq;
    __nv_bfloat16* out = g_qhat + (size_t)b * D_SZ + t * 4;
    out[0] = __float2bfloat16(a.x * rq);
    out[1] = __float2bfloat16(a.y * rq);
    out[2] = __float2bfloat16(a.z * rq);
    out[3] = __float2bfloat16(a.w * rq);
}

// ---------------------------------------------------------------------------
// Kernel 2: prep negatives -> nhat (bf16)
// ---------------------------------------------------------------------------
__global__ __launch_bounds__(256) void prep_n_kernel(const float* __restrict__ nkeys) {
    const int nrow = blockIdx.x;
    const int t = threadIdx.x;
    const float4* n4 = (const float4*)(nkeys + (size_t)nrow * D_SZ);
    float4 a = n4[t];
    float nn = a.x * a.x + a.y * a.y + a.z * a.z + a.w * a.w;
    #pragma unroll
    for (int off = 16; off > 0; off >>= 1) nn += __shfl_xor_sync(0xffffffff, nn, off);
    __shared__ float sn[8], s_rn;
    const int wid = t >> 5, lane = t & 31;
    if (lane == 0) sn[wid] = nn;
    __syncthreads();
    if (t == 0) {
        float tn = 0.f;
        #pragma unroll
        for (int i = 0; i < 8; i++) tn += sn[i];
        float norm = sqrtf(tn);
        s_rn = (norm > 0.f) ? (1.0f / norm) : 0.0f;
    }
    __syncthreads();
    const float rn = s_rn;
    __nv_bfloat16* out = g_nhat + (size_t)nrow * D_SZ + t * 4;
    out[0] = __float2bfloat16(a.x * rn);
    out[1] = __float2bfloat16(a.y * rn);
    out[2] = __float2bfloat16(a.z * rn);
    out[3] = __float2bfloat16(a.w * rn);
}

// ---------------------------------------------------------------------------
// Kernel 3 (position filler + real init): zero loss; keeps GEMM at launch #4
// for the ncu capture slot.
// ---------------------------------------------------------------------------
__global__ void init_loss_kernel() {
    if (threadIdx.x == 0) g_loss = 0.0f;
}

// ---------------------------------------------------------------------------
// Kernel 4: raw mma.sync GEMM (bf16->fp32) + register-resident exp/rowsum.
//   Block: 128(M) x 256(N), 256 threads (8 warps, 2x4), warp tile 64x64.
//   K chunk 128, 2-stage cp.async. Fragment loads double-buffered across kk.
// ---------------------------------------------------------------------------
#define BM 128
#define BN 256
#define KC 128
#define CHUNKS (D_SZ / KC)        // 8
#define KP 136                    // smem row pitch in bf16 elems
#define KPB (KP * 2)              // 272 bytes
#define A_STB (BM * KPB)          // 34816 B
#define B_STB (BN * KPB)          // 69632 B
#define STAGE_B (A_STB + B_STB)   // 104448 B
#define SMEM_BYTES (2 * STAGE_B)  // 208896

__global__ __launch_bounds__(256, 1) void gemm_exp_kernel() {
    extern __shared__ __nv_bfloat16 sm[];
    const int tid = threadIdx.x;
    const int wid = tid >> 5, lane = tid & 31;
    const int wm = wid >> 2;          // 0..1 -> 64-row strip
    const int wn = wid & 3;           // 0..3 -> 64-col strip
    const int m0 = blockIdx.y * BM;
    const int n0 = blockIdx.x * BN;
    const uint32_t sbase = smem_u32(sm);

    // ---- cp.async slots (same proven layout as R6) ----
    const int r0 = tid >> 4;          // 0..15
    const int seg = tid & 15;         // 0..15
    const uint32_t a_soff0 = (uint32_t)(r0 * KP + seg * 8) * 2;
    const uint32_t b_soff0 = (uint32_t)A_STB + (uint32_t)(r0 * KP + seg * 8) * 2;
    const __nv_bfloat16* a_ptr = g_qhat + (size_t)(m0 + r0) * D_SZ + seg * 8;
    const __nv_bfloat16* b_ptr = g_nhat + (size_t)(n0 + r0) * D_SZ + seg * 8;
    const uint32_t row_soff = 16u * KPB;
    const uint32_t row_goff = 16u * D_SZ;

    // ---- ldmatrix per-lane base offsets (stage-relative bytes) ----
    // x4 tiles: jj=lane>>3 -> tile; rows (jj&1)*8+lane%8; cols (jj>>1)*8.
    const int lane8 = lane & 7;
    const int jj = lane >> 3;
    const uint32_t lm_row = ((jj & 1) << 3) + lane8;
    const uint32_t lm_col = (uint32_t)(jj >> 1) << 4;   // bytes (8 elems)
    uint32_t a_base[4], b_base[4];
    #pragma unroll
    for (int mf = 0; mf < 4; mf++)
        a_base[mf] = (uint32_t)((wm * 64 + mf * 16 + lm_row) * KPB) + lm_col;
    #pragma unroll
    for (int nt = 0; nt < 4; nt++)
        b_base[nt] = (uint32_t)A_STB + (uint32_t)((wn * 64 + nt * 16 + lm_row) * KPB) + lm_col;

    float acc[4][8][4];
    #pragma unroll
    for (int mf = 0; mf < 4; mf++)
        #pragma unroll
        for (int nf = 0; nf < 8; nf++)
            #pragma unroll
            for (int i = 0; i < 4; i++)
                acc[mf][nf][i] = 0.0f;

    // Prologue: chunk 0 into slot 0
    {
        #pragma unroll
        for (int i = 0; i < 8; i++)
            CP_ASYNC16(sbase + a_soff0 + i * row_soff, a_ptr + i * row_goff);
        #pragma unroll
        for (int i = 0; i < 16; i++)
            CP_ASYNC16(sbase + b_soff0 + i * row_soff, b_ptr + i * row_goff);
        CP_COMMIT();
    }

    for (int kt = 0; kt < CHUNKS; kt++) {
        if (kt + 1 < CHUNKS) {
            uint32_t st = sbase + ((kt + 1) & 1) * STAGE_B;
            int k0 = (kt + 1) * KC;
            #pragma unroll
            for (int i = 0; i < 8; i++)
                CP_ASYNC16(st + a_soff0 + i * row_soff, a_ptr + i * row_goff + k0);
            #pragma unroll
            for (int i = 0; i < 16; i++)
                CP_ASYNC16(st + b_soff0 + i * row_soff, b_ptr + i * row_goff + k0);
            CP_COMMIT();
            CP_WAIT1();
        } else {
            CP_WAIT0();
        }
        __syncthreads();

        const uint32_t so = sbase + (kt & 1) * STAGE_B;

        // Fragment double-buffer across the 8 k-steps of this chunk.
        uint32_t afr[2][16], bfr[2][16];
        #pragma unroll
        for (int mf = 0; mf < 4; mf++) ldsm4(&afr[0][mf * 4], so + a_base[mf]);
        #pragma unroll
        for (int nt = 0; nt < 4; nt++) ldsm4(&bfr[0][nt * 4], so + b_base[nt]);

        #pragma unroll
        for (int kk = 0; kk < 8; kk++) {
            const int cur = kk & 1;
            if (kk < 7) {
                const uint32_t ko = (uint32_t)(kk + 1) * 32u;
                #pragma unroll
                for (int mf = 0; mf < 4; mf++)
                    ldsm4(&afr[cur ^ 1][mf * 4], so + a_base[mf] + ko);
                #pragma unroll
                for (int nt = 0; nt < 4; nt++)
                    ldsm4(&bfr[cur ^ 1][nt * 4], so + b_base[nt] + ko);
            }
            #pragma unroll
            for (int mf = 0; mf < 4; mf++)
                #pragma unroll
                for (int nf = 0; nf < 8; nf++) {
                    const int nt = nf >> 1, h = nf & 1;
                    // tile regs: r0=lower-n8 b0, r1=upper-n8 b0, r2=lower b1, r3=upper b1
                    mma16816(acc[mf][nf], &afr[cur][mf * 4],
                             bfr[cur][nt * 4 + h], bfr[cur][nt * 4 + h + 2]);
                }
        }
        __syncthreads();   // protect slot (kt&1) before refill at kt+2
    }

    // ---- register-resident epilogue: exp + rowsum + quad-reduce ----
    // Thread t holds rows (t/4) and (t/4)+8 of each 16-row mf strip.
    #pragma unroll
    for (int mf = 0; mf < 4; mf++) {
        float lo = 0.0f, hi = 0.0f;
        #pragma unroll
        for (int nf = 0; nf < 8; nf++) {
            lo += __expf(acc[mf][nf][0] * INV_T) + __expf(acc[mf][nf][1] * INV_T);
            hi += __expf(acc[mf][nf][2] * INV_T) + __expf(acc[mf][nf][3] * INV_T);
        }
        // reduce across the 4 threads sharing each row (lane%4)
        #pragma unroll
        for (int off = 1; off < 4; off <<= 1) {
            lo += __shfl_xor_sync(0xffffffff, lo, off);
            hi += __shfl_xor_sync(0xffffffff, hi, off);
        }
        if ((lane & 3) == 0) {
            const int rbase = m0 + wm * 64 + mf * 16 + (lane >> 2);
            atomicAdd(&g_S2[rbase], lo);
            atomicAdd(&g_S2[rbase + 8], hi);
        }
    }
}

// ---------------------------------------------------------------------------
// Kernel 5/6: per-row loss terms -> g_loss; write out.
// ---------------------------------------------------------------------------
__global__ __launch_bounds__(256) void finalize_partial_kernel() {
    const int b = blockIdx.x * 256 + threadIdx.x;
    float s1 = g_s1[b];
    float s2 = g_S2[b] * (1.0f / (float)N_SZ);
    float v = -logf(s1 / (s1 + s2));

    __shared__ float sd[256];
    sd[threadIdx.x] = v;
    __syncthreads();
    #pragma unroll
    for (int stride = 128; stride > 0; stride >>= 1) {
        if (threadIdx.x < stride) sd[threadIdx.x] += sd[threadIdx.x + stride];
        __syncthreads();
    }
    if (threadIdx.x == 0) atomicAdd(&g_loss, sd[0]);
}

__global__ void finalize_write_kernel(float* __restrict__ out) {
    out[0] = g_loss * (1.0f / (float)B_SZ);
}

// ---------------------------------------------------------------------------
extern "C" void kernel_launch(void* const* d_in, const int* in_sizes, int n_in,
                              void* d_out, int out_size) {
    const float* q  = (const float*)d_in[0];
    const float* p  = (const float*)d_in[1];
    const float* nk = (const float*)d_in[2];
    float* out = (float*)d_out;

    cudaFuncSetAttribute(gemm_exp_kernel,
                         cudaFuncAttributeMaxDynamicSharedMemorySize, SMEM_BYTES);

    prep_qp_kernel<<<B_SZ, 256>>>(q, p);
    prep_n_kernel<<<N_SZ, 256>>>(nk);
    init_loss_kernel<<<1, 32>>>();
    gemm_exp_kernel<<<dim3(N_SZ / BN, B_SZ / BM), 256, SMEM_BYTES>>>();
    finalize_partial_kernel<<<B_SZ / 256, 256>>>();
    finalize_write_kernel<<<1, 1>>>(out);
}

// round 9
// speedup vs baseline: 1.5080x; 1.5080x over previous
#include <cuda_runtime.h>
#include <cuda_bf16.h>
#include <mma.h>
#include <cstdint>

using namespace nvcuda;

#define B_SZ 8192
#define N_SZ 8192
#define D_SZ 1024
#define EPS_F 1e-6f
constexpr float INV_T = 1.0f / 0.92f;

// ---------------- scratch (device globals; no allocations allowed) ----------
__device__ __nv_bfloat16 g_qhat[(size_t)B_SZ * D_SZ]; // 16 MB
__device__ __nv_bfloat16 g_nhat[(size_t)N_SZ * D_SZ]; // 16 MB
__device__ float g_s1[B_SZ];
__device__ float g_S2[B_SZ];
__device__ float g_loss;

// ---------------------------------------------------------------------------
#define CP_ASYNC16(dst, src) \
    asm volatile("cp.async.cg.shared.global [%0], [%1], 16;" :: "r"(dst), "l"(src) : "memory")
#define CP_COMMIT() asm volatile("cp.async.commit_group;" ::: "memory")
#define CP_WAIT1()  asm volatile("cp.async.wait_group 1;" ::: "memory")
#define CP_WAIT0()  asm volatile("cp.async.wait_group 0;" ::: "memory")

__device__ __forceinline__ uint32_t smem_u32(const void* p) {
    uint32_t a;
    asm("{ .reg .u64 t; cvta.to.shared.u64 t, %1; cvt.u32.u64 %0, t; }"
        : "=r"(a) : "l"(p));
    return a;
}

// ---------------------------------------------------------------------------
// Kernel 1: prep q,p -> qhat (bf16), s1, zero S2
// ---------------------------------------------------------------------------
__global__ __launch_bounds__(256) void prep_qp_kernel(const float* __restrict__ q,
                                                      const float* __restrict__ p) {
    const int b = blockIdx.x;
    const int t = threadIdx.x;
    const float4* q4 = (const float4*)(q + (size_t)b * D_SZ);
    const float4* p4 = (const float4*)(p + (size_t)b * D_SZ);

    float4 a = q4[t];
    float4 c = p4[t];
    float qq = a.x * a.x + a.y * a.y + a.z * a.z + a.w * a.w;
    float pp = c.x * c.x + c.y * c.y + c.z * c.z + c.w * c.w;
    float qp = a.x * c.x + a.y * c.y + a.z * c.z + a.w * c.w;

    #pragma unroll
    for (int off = 16; off > 0; off >>= 1) {
        qq += __shfl_xor_sync(0xffffffff, qq, off);
        pp += __shfl_xor_sync(0xffffffff, pp, off);
        qp += __shfl_xor_sync(0xffffffff, qp, off);
    }
    __shared__ float sq[8], sp[8], sqp[8], s_rq;
    const int wid = t >> 5, lane = t & 31;
    if (lane == 0) { sq[wid] = qq; sp[wid] = pp; sqp[wid] = qp; }
    __syncthreads();
    if (t == 0) {
        float tq = 0.f, tp = 0.f, tqp = 0.f;
        #pragma unroll
        for (int i = 0; i < 8; i++) { tq += sq[i]; tp += sp[i]; tqp += sqp[i]; }
        float qn = sqrtf(tq), pn = sqrtf(tp);
        float pos = tqp / fmaxf(qn * pn, EPS_F);
        g_s1[b] = __expf(pos * INV_T);
        g_S2[b] = 0.0f;
        s_rq = (qn > 0.f) ? (1.0f / qn) : 0.0f;
    }
    __syncthreads();
    const float rq = s_rq;
    __nv_bfloat16* out = g_qhat + (size_t)b * D_SZ + t * 4;
    out[0] = __float2bfloat16(a.x * rq);
    out[1] = __float2bfloat16(a.y * rq);
    out[2] = __float2bfloat16(a.z * rq);
    out[3] = __float2bfloat16(a.w * rq);
}

// ---------------------------------------------------------------------------
// Kernel 2: prep negatives -> nhat (bf16)
// ---------------------------------------------------------------------------
__global__ __launch_bounds__(256) void prep_n_kernel(const float* __restrict__ nkeys) {
    const int nrow = blockIdx.x;
    const int t = threadIdx.x;
    const float4* n4 = (const float4*)(nkeys + (size_t)nrow * D_SZ);
    float4 a = n4[t];
    float nn = a.x * a.x + a.y * a.y + a.z * a.z + a.w * a.w;
    #pragma unroll
    for (int off = 16; off > 0; off >>= 1) nn += __shfl_xor_sync(0xffffffff, nn, off);
    __shared__ float sn[8], s_rn;
    const int wid = t >> 5, lane = t & 31;
    if (lane == 0) sn[wid] = nn;
    __syncthreads();
    if (t == 0) {
        float tn = 0.f;
        #pragma unroll
        for (int i = 0; i < 8; i++) tn += sn[i];
        float norm = sqrtf(tn);
        s_rn = (norm > 0.f) ? (1.0f / norm) : 0.0f;
    }
    __syncthreads();
    const float rn = s_rn;
    __nv_bfloat16* out = g_nhat + (size_t)nrow * D_SZ + t * 4;
    out[0] = __float2bfloat16(a.x * rn);
    out[1] = __float2bfloat16(a.y * rn);
    out[2] = __float2bfloat16(a.z * rn);
    out[3] = __float2bfloat16(a.w * rn);
}

// ---------------------------------------------------------------------------
// Kernel 3: zero loss; keeps GEMM at captured launch slot #4.
// ---------------------------------------------------------------------------
__global__ void init_loss_kernel() {
    if (threadIdx.x == 0) g_loss = 0.0f;
}

// ---------------------------------------------------------------------------
// Kernel 4: wmma GEMM (bf16->fp32) + fused exp/rowsum, 2-stage cp.async.
//   Block: 128(M) x 128(N), 256 threads (8 warps, 4x2), warp tile 32x64.
//   KC=64, pitch 72 (144B rows), 2 stages = 73.7KB -> 2 CTAs/SM.
//   __launch_bounds__(256,2) caps regs at 128 (acc=64 + frags ~24).
// ---------------------------------------------------------------------------
#define BM 128
#define BN 128
#define KC 64
#define CHUNKS (D_SZ / KC)        // 16
#define KP 72                     // smem row pitch in bf16 elems (144B)
#define A_ST (BM * KP)            // 9216 elems
#define B_ST (BN * KP)            // 9216 elems
#define STAGE_ELEMS (A_ST + B_ST) // 18432 elems = 36864 B
#define SMEM_BYTES (2 * STAGE_ELEMS * 2)   // 73728
#define CP 20

__global__ __launch_bounds__(256, 2) void gemm_exp_kernel() {
    extern __shared__ __nv_bfloat16 sm[];
    const int tid = threadIdx.x;
    const int wid = tid >> 5, lane = tid & 31;
    const int wm = wid >> 1;          // 0..3 -> 32-row strip
    const int wn = wid & 1;           // 0..1 -> 64-col strip
    const int m0 = blockIdx.y * BM;
    const int n0 = blockIdx.x * BN;
    const uint32_t sbase = smem_u32(sm);

    // cp.async: rows have 8 16B segs (64 bf16 = 128B).
    //   A: 128*8 = 1024 vecs -> 4/thread; B same.
    const int r0 = tid >> 3;          // 0..31
    const int seg = tid & 7;          // 0..7
    const uint32_t a_soff0 = (uint32_t)(r0 * KP + seg * 8) * 2;
    const uint32_t b_soff0 = (uint32_t)(A_ST + r0 * KP + seg * 8) * 2;
    const __nv_bfloat16* a_ptr = g_qhat + (size_t)(m0 + r0) * D_SZ + seg * 8;
    const __nv_bfloat16* b_ptr = g_nhat + (size_t)(n0 + r0) * D_SZ + seg * 8;
    const uint32_t row_soff = 32u * KP * 2;      // smem bytes per 32-row step
    const uint32_t row_goff = 32u * D_SZ;        // gmem elems per 32-row step

    wmma::fragment<wmma::accumulator, 16, 16, 16, float> acc[2][4];
    #pragma unroll
    for (int mf = 0; mf < 2; mf++)
        #pragma unroll
        for (int nf = 0; nf < 4; nf++)
            wmma::fill_fragment(acc[mf][nf], 0.0f);

    // Prologue: chunk 0 into slot 0
    {
        #pragma unroll
        for (int i = 0; i < 4; i++) {
            CP_ASYNC16(sbase + a_soff0 + i * row_soff, a_ptr + i * row_goff);
            CP_ASYNC16(sbase + b_soff0 + i * row_soff, b_ptr + i * row_goff);
        }
        CP_COMMIT();
    }

    for (int kt = 0; kt < CHUNKS; kt++) {
        if (kt + 1 < CHUNKS) {
            uint32_t st = sbase + ((kt + 1) & 1) * (STAGE_ELEMS * 2);
            int k0 = (kt + 1) * KC;
            #pragma unroll
            for (int i = 0; i < 4; i++) {
                CP_ASYNC16(st + a_soff0 + i * row_soff, a_ptr + i * row_goff + k0);
                CP_ASYNC16(st + b_soff0 + i * row_soff, b_ptr + i * row_goff + k0);
            }
            CP_COMMIT();
            CP_WAIT1();
        } else {
            CP_WAIT0();
        }
        __syncthreads();

        const __nv_bfloat16* As = sm + (kt & 1) * STAGE_ELEMS;
        const __nv_bfloat16* Bs = As + A_ST;
        #pragma unroll
        for (int kk = 0; kk < 4; kk++) {
            wmma::fragment<wmma::matrix_a, 16, 16, 16, __nv_bfloat16, wmma::row_major> af[2];
            #pragma unroll
            for (int mf = 0; mf < 2; mf++)
                wmma::load_matrix_sync(af[mf], As + (wm * 32 + mf * 16) * KP + kk * 16, KP);
            #pragma unroll
            for (int nf = 0; nf < 4; nf++) {
                wmma::fragment<wmma::matrix_b, 16, 16, 16, __nv_bfloat16, wmma::col_major> bf;
                wmma::load_matrix_sync(bf, Bs + (wn * 64 + nf * 16) * KP + kk * 16, KP);
                #pragma unroll
                for (int mf = 0; mf < 2; mf++)
                    wmma::mma_sync(acc[mf][nf], af[mf], bf, acc[mf][nf]);
            }
        }
        __syncthreads();   // protect slot (kt&1) before refill at kt+2
    }

    // Epilogue: overlay scratch on pipeline smem (all loads/MMA done).
    float* scratch = (float*)sm + wid * (16 * CP);
    #pragma unroll
    for (int mf = 0; mf < 2; mf++) {
        float partial = 0.0f;
        #pragma unroll
        for (int nf = 0; nf < 4; nf++) {
            wmma::store_matrix_sync(scratch, acc[mf][nf], CP, wmma::mem_row_major);
            __syncwarp();
            const int r = lane & 15, h = lane >> 4;
            const float* pr = scratch + r * CP + h * 8;
            #pragma unroll
            for (int c = 0; c < 8; c++) partial += __expf(pr[c] * INV_T);
            __syncwarp();
        }
        partial += __shfl_xor_sync(0xffffffff, partial, 16);
        if (lane < 16)
            atomicAdd(&g_S2[m0 + wm * 32 + mf * 16 + lane], partial);
    }
}

// ---------------------------------------------------------------------------
// Kernel 5/6: per-row loss terms -> g_loss; write out.
// ---------------------------------------------------------------------------
__global__ __launch_bounds__(256) void finalize_partial_kernel() {
    const int b = blockIdx.x * 256 + threadIdx.x;
    float s1 = g_s1[b];
    float s2 = g_S2[b] * (1.0f / (float)N_SZ);
    float v = -logf(s1 / (s1 + s2));

    __shared__ float sd[256];
    sd[threadIdx.x] = v;
    __syncthreads();
    #pragma unroll
    for (int stride = 128; stride > 0; stride >>= 1) {
        if (threadIdx.x < stride) sd[threadIdx.x] += sd[threadIdx.x + stride];
        __syncthreads();
    }
    if (threadIdx.x == 0) atomicAdd(&g_loss, sd[0]);
}

__global__ void finalize_write_kernel(float* __restrict__ out) {
    out[0] = g_loss * (1.0f / (float)B_SZ);
}

// ---------------------------------------------------------------------------
extern "C" void kernel_launch(void* const* d_in, const int* in_sizes, int n_in,
                              void* d_out, int out_size) {
    const float* q  = (const float*)d_in[0];
    const float* p  = (const float*)d_in[1];
    const float* nk = (const float*)d_in[2];
    float* out = (float*)d_out;

    cudaFuncSetAttribute(gemm_exp_kernel,
                         cudaFuncAttributeMaxDynamicSharedMemorySize, SMEM_BYTES);

    prep_qp_kernel<<<B_SZ, 256>>>(q, p);
    prep_n_kernel<<<N_SZ, 256>>>(nk);
    init_loss_kernel<<<1, 32>>>();
    gemm_exp_kernel<<<dim3(N_SZ / BN, B_SZ / BM), 256, SMEM_BYTES>>>();
    finalize_partial_kernel<<<B_SZ / 256, 256>>>();
    finalize_write_kernel<<<1, 1>>>(out);
}

// round 10
// speedup vs baseline: 1.5186x; 1.0070x over previous
#include <cuda_runtime.h>
#include <cuda_bf16.h>
#include <mma.h>
#include <cstdint>

using namespace nvcuda;

#define B_SZ 8192
#define N_SZ 8192
#define D_SZ 1024
#define EPS_F 1e-6f
constexpr float INV_T = 1.0f / 0.92f;

// ---------------- scratch (device globals; no allocations allowed) ----------
__device__ __nv_bfloat16 g_qhat[(size_t)B_SZ * D_SZ]; // 16 MB
__device__ __nv_bfloat16 g_nhat[(size_t)N_SZ * D_SZ]; // 16 MB
__device__ float g_s1[B_SZ];
__device__ float g_S2[B_SZ];
__device__ float g_loss;

// ---------------------------------------------------------------------------
#define CP_ASYNC16(dst, src) \
    asm volatile("cp.async.cg.shared.global [%0], [%1], 16;" :: "r"(dst), "l"(src) : "memory")
#define CP_COMMIT() asm volatile("cp.async.commit_group;" ::: "memory")
#define CP_WAIT1()  asm volatile("cp.async.wait_group 1;" ::: "memory")
#define CP_WAIT0()  asm volatile("cp.async.wait_group 0;" ::: "memory")

__device__ __forceinline__ uint32_t smem_u32(const void* p) {
    uint32_t a;
    asm("{ .reg .u64 t; cvta.to.shared.u64 t, %1; cvt.u32.u64 %0, t; }"
        : "=r"(a) : "l"(p));
    return a;
}

// ---------------------------------------------------------------------------
// Kernel 1: prep q,p -> qhat (bf16), s1, zero S2
// ---------------------------------------------------------------------------
__global__ __launch_bounds__(256) void prep_qp_kernel(const float* __restrict__ q,
                                                      const float* __restrict__ p) {
    const int b = blockIdx.x;
    const int t = threadIdx.x;
    const float4* q4 = (const float4*)(q + (size_t)b * D_SZ);
    const float4* p4 = (const float4*)(p + (size_t)b * D_SZ);

    float4 a = q4[t];
    float4 c = p4[t];
    float qq = a.x * a.x + a.y * a.y + a.z * a.z + a.w * a.w;
    float pp = c.x * c.x + c.y * c.y + c.z * c.z + c.w * c.w;
    float qp = a.x * c.x + a.y * c.y + a.z * c.z + a.w * c.w;

    #pragma unroll
    for (int off = 16; off > 0; off >>= 1) {
        qq += __shfl_xor_sync(0xffffffff, qq, off);
        pp += __shfl_xor_sync(0xffffffff, pp, off);
        qp += __shfl_xor_sync(0xffffffff, qp, off);
    }
    __shared__ float sq[8], sp[8], sqp[8], s_rq;
    const int wid = t >> 5, lane = t & 31;
    if (lane == 0) { sq[wid] = qq; sp[wid] = pp; sqp[wid] = qp; }
    __syncthreads();
    if (t == 0) {
        float tq = 0.f, tp = 0.f, tqp = 0.f;
        #pragma unroll
        for (int i = 0; i < 8; i++) { tq += sq[i]; tp += sp[i]; tqp += sqp[i]; }
        float qn = sqrtf(tq), pn = sqrtf(tp);
        float pos = tqp / fmaxf(qn * pn, EPS_F);
        g_s1[b] = __expf(pos * INV_T);
        g_S2[b] = 0.0f;
        s_rq = (qn > 0.f) ? (1.0f / qn) : 0.0f;
    }
    __syncthreads();
    const float rq = s_rq;
    __nv_bfloat16* out = g_qhat + (size_t)b * D_SZ + t * 4;
    out[0] = __float2bfloat16(a.x * rq);
    out[1] = __float2bfloat16(a.y * rq);
    out[2] = __float2bfloat16(a.z * rq);
    out[3] = __float2bfloat16(a.w * rq);
}

// ---------------------------------------------------------------------------
// Kernel 2: prep negatives -> nhat (bf16)
// ---------------------------------------------------------------------------
__global__ __launch_bounds__(256) void prep_n_kernel(const float* __restrict__ nkeys) {
    const int nrow = blockIdx.x;
    const int t = threadIdx.x;
    const float4* n4 = (const float4*)(nkeys + (size_t)nrow * D_SZ);
    float4 a = n4[t];
    float nn = a.x * a.x + a.y * a.y + a.z * a.z + a.w * a.w;
    #pragma unroll
    for (int off = 16; off > 0; off >>= 1) nn += __shfl_xor_sync(0xffffffff, nn, off);
    __shared__ float sn[8], s_rn;
    const int wid = t >> 5, lane = t & 31;
    if (lane == 0) sn[wid] = nn;
    __syncthreads();
    if (t == 0) {
        float tn = 0.f;
        #pragma unroll
        for (int i = 0; i < 8; i++) tn += sn[i];
        float norm = sqrtf(tn);
        s_rn = (norm > 0.f) ? (1.0f / norm) : 0.0f;
    }
    __syncthreads();
    const float rn = s_rn;
    __nv_bfloat16* out = g_nhat + (size_t)nrow * D_SZ + t * 4;
    out[0] = __float2bfloat16(a.x * rn);
    out[1] = __float2bfloat16(a.y * rn);
    out[2] = __float2bfloat16(a.z * rn);
    out[3] = __float2bfloat16(a.w * rn);
}

// ---------------------------------------------------------------------------
// Kernel 3: zero loss; keeps GEMM at captured launch slot #4.
// ---------------------------------------------------------------------------
__global__ void init_loss_kernel() {
    if (threadIdx.x == 0) g_loss = 0.0f;
}

// ---------------------------------------------------------------------------
// Kernel 4: wmma GEMM + fused exp/rowsum. 2-stage cp.async, 2 CTAs/SM,
//   block 128x128, 8 warps (4x2), warp tile 32x64.
//   NEW: wmma fragments double-buffered across the 4 k-steps of each chunk
//   so LDSM(kk+1) overlaps HMMA(kk) - breaks the LDSM/HMMA phase alternation.
// ---------------------------------------------------------------------------
#define BM 128
#define BN 128
#define KC 64
#define CHUNKS (D_SZ / KC)        // 16
#define KP 72                     // smem row pitch in bf16 elems (144B)
#define A_ST (BM * KP)
#define B_ST (BN * KP)
#define STAGE_ELEMS (A_ST + B_ST) // 18432 elems = 36864 B
#define SMEM_BYTES (2 * STAGE_ELEMS * 2)   // 73728
#define CP 20

__global__ __launch_bounds__(256, 2) void gemm_exp_kernel() {
    extern __shared__ __nv_bfloat16 sm[];
    const int tid = threadIdx.x;
    const int wid = tid >> 5, lane = tid & 31;
    const int wm = wid >> 1;          // 0..3 -> 32-row strip
    const int wn = wid & 1;           // 0..1 -> 64-col strip
    const int m0 = blockIdx.y * BM;
    const int n0 = blockIdx.x * BN;
    const uint32_t sbase = smem_u32(sm);

    const int r0 = tid >> 3;          // 0..31
    const int seg = tid & 7;          // 0..7
    const uint32_t a_soff0 = (uint32_t)(r0 * KP + seg * 8) * 2;
    const uint32_t b_soff0 = (uint32_t)(A_ST + r0 * KP + seg * 8) * 2;
    const __nv_bfloat16* a_ptr = g_qhat + (size_t)(m0 + r0) * D_SZ + seg * 8;
    const __nv_bfloat16* b_ptr = g_nhat + (size_t)(n0 + r0) * D_SZ + seg * 8;
    const uint32_t row_soff = 32u * KP * 2;
    const uint32_t row_goff = 32u * D_SZ;

    wmma::fragment<wmma::accumulator, 16, 16, 16, float> acc[2][4];
    #pragma unroll
    for (int mf = 0; mf < 2; mf++)
        #pragma unroll
        for (int nf = 0; nf < 4; nf++)
            wmma::fill_fragment(acc[mf][nf], 0.0f);

    // Prologue: chunk 0 into slot 0
    {
        #pragma unroll
        for (int i = 0; i < 4; i++) {
            CP_ASYNC16(sbase + a_soff0 + i * row_soff, a_ptr + i * row_goff);
            CP_ASYNC16(sbase + b_soff0 + i * row_soff, b_ptr + i * row_goff);
        }
        CP_COMMIT();
    }

    for (int kt = 0; kt < CHUNKS; kt++) {
        if (kt + 1 < CHUNKS) {
            uint32_t st = sbase + ((kt + 1) & 1) * (STAGE_ELEMS * 2);
            int k0 = (kt + 1) * KC;
            #pragma unroll
            for (int i = 0; i < 4; i++) {
                CP_ASYNC16(st + a_soff0 + i * row_soff, a_ptr + i * row_goff + k0);
                CP_ASYNC16(st + b_soff0 + i * row_soff, b_ptr + i * row_goff + k0);
            }
            CP_COMMIT();
            CP_WAIT1();
        } else {
            CP_WAIT0();
        }
        __syncthreads();

        const __nv_bfloat16* As = sm + (kt & 1) * STAGE_ELEMS;
        const __nv_bfloat16* Bs = As + A_ST;

        // Fragment double-buffer across the 4 k-steps.
        wmma::fragment<wmma::matrix_a, 16, 16, 16, __nv_bfloat16, wmma::row_major> af[2][2];
        wmma::fragment<wmma::matrix_b, 16, 16, 16, __nv_bfloat16, wmma::col_major> bf[2][4];
        #pragma unroll
        for (int mf = 0; mf < 2; mf++)
            wmma::load_matrix_sync(af[0][mf], As + (wm * 32 + mf * 16) * KP, KP);
        #pragma unroll
        for (int nf = 0; nf < 4; nf++)
            wmma::load_matrix_sync(bf[0][nf], Bs + (wn * 64 + nf * 16) * KP, KP);

        #pragma unroll
        for (int kk = 0; kk < 4; kk++) {
            const int cur = kk & 1, nxt = cur ^ 1;
            if (kk < 3) {
                #pragma unroll
                for (int mf = 0; mf < 2; mf++)
                    wmma::load_matrix_sync(af[nxt][mf],
                        As + (wm * 32 + mf * 16) * KP + (kk + 1) * 16, KP);
                #pragma unroll
                for (int nf = 0; nf < 4; nf++)
                    wmma::load_matrix_sync(bf[nxt][nf],
                        Bs + (wn * 64 + nf * 16) * KP + (kk + 1) * 16, KP);
            }
            #pragma unroll
            for (int nf = 0; nf < 4; nf++)
                #pragma unroll
                for (int mf = 0; mf < 2; mf++)
                    wmma::mma_sync(acc[mf][nf], af[cur][mf], bf[cur][nf], acc[mf][nf]);
        }
        __syncthreads();   // protect slot (kt&1) before refill at kt+2
    }

    // Epilogue: overlay scratch on pipeline smem (all loads/MMA done).
    float* scratch = (float*)sm + wid * (16 * CP);
    #pragma unroll
    for (int mf = 0; mf < 2; mf++) {
        float partial = 0.0f;
        #pragma unroll
        for (int nf = 0; nf < 4; nf++) {
            wmma::store_matrix_sync(scratch, acc[mf][nf], CP, wmma::mem_row_major);
            __syncwarp();
            const int r = lane & 15, h = lane >> 4;
            const float* pr = scratch + r * CP + h * 8;
            #pragma unroll
            for (int c = 0; c < 8; c++) partial += __expf(pr[c] * INV_T);
            __syncwarp();
        }
        partial += __shfl_xor_sync(0xffffffff, partial, 16);
        if (lane < 16)
            atomicAdd(&g_S2[m0 + wm * 32 + mf * 16 + lane], partial);
    }
}

// ---------------------------------------------------------------------------
// Kernel 5/6: per-row loss terms -> g_loss; write out.
// ---------------------------------------------------------------------------
__global__ __launch_bounds__(256) void finalize_partial_kernel() {
    const int b = blockIdx.x * 256 + threadIdx.x;
    float s1 = g_s1[b];
    float s2 = g_S2[b] * (1.0f / (float)N_SZ);
    float v = -logf(s1 / (s1 + s2));

    __shared__ float sd[256];
    sd[threadIdx.x] = v;
    __syncthreads();
    #pragma unroll
    for (int stride = 128; stride > 0; stride >>= 1) {
        if (threadIdx.x < stride) sd[threadIdx.x] += sd[threadIdx.x + stride];
        __syncthreads();
    }
    if (threadIdx.x == 0) atomicAdd(&g_loss, sd[0]);
}

__global__ void finalize_write_kernel(float* __restrict__ out) {
    out[0] = g_loss * (1.0f / (float)B_SZ);
}

// ---------------------------------------------------------------------------
extern "C" void kernel_launch(void* const* d_in, const int* in_sizes, int n_in,
                              void* d_out, int out_size) {
    const float* q  = (const float*)d_in[0];
    const float* p  = (const float*)d_in[1];
    const float* nk = (const float*)d_in[2];
    float* out = (float*)d_out;

    cudaFuncSetAttribute(gemm_exp_kernel,
                         cudaFuncAttributeMaxDynamicSharedMemorySize, SMEM_BYTES);

    prep_qp_kernel<<<B_SZ, 256>>>(q, p);
    prep_n_kernel<<<N_SZ, 256>>>(nk);
    init_loss_kernel<<<1, 32>>>();
    gemm_exp_kernel<<<dim3(N_SZ / BN, B_SZ / BM), 256, SMEM_BYTES>>>();
    finalize_partial_kernel<<<B_SZ / 256, 256>>>();
    finalize_write_kernel<<<1, 1>>>(out);
}

// round 11
// speedup vs baseline: 1.9233x; 1.2665x over previous
#include <cuda_runtime.h>
#include <cuda_bf16.h>
#include <cuda_fp16.h>
#include <mma.h>
#include <cstdint>

using namespace nvcuda;

#define B_SZ 8192
#define N_SZ 8192
#define D_SZ 1024
#define EPS_F 1e-6f
constexpr float INV_T = 1.0f / 0.92f;

// ---------------- scratch (device globals; no allocations allowed) ----------
__device__ __half g_qhat[(size_t)B_SZ * D_SZ]; // 16 MB (fp16 normalized q)
__device__ __half g_nhat[(size_t)N_SZ * D_SZ]; // 16 MB (fp16 normalized n)
__device__ float g_s1[B_SZ];
__device__ float g_S2[B_SZ];
__device__ float g_loss;

// ---------------------------------------------------------------------------
#define CP_ASYNC16(dst, src) \
    asm volatile("cp.async.cg.shared.global [%0], [%1], 16;" :: "r"(dst), "l"(src) : "memory")
#define CP_COMMIT() asm volatile("cp.async.commit_group;" ::: "memory")
#define CP_WAIT1()  asm volatile("cp.async.wait_group 1;" ::: "memory")
#define CP_WAIT0()  asm volatile("cp.async.wait_group 0;" ::: "memory")

__device__ __forceinline__ uint32_t smem_u32(const void* p) {
    uint32_t a;
    asm("{ .reg .u64 t; cvta.to.shared.u64 t, %1; cvt.u32.u64 %0, t; }"
        : "=r"(a) : "l"(p));
    return a;
}

// ---------------------------------------------------------------------------
// Kernel 1: prep q,p -> qhat (fp16), s1, zero S2
// (values are unit-vector components ~0.03 -> fp16 range trivially fine,
//  fp16 has 11-bit mantissa: quantization BETTER than bf16)
// ---------------------------------------------------------------------------
__global__ __launch_bounds__(256) void prep_qp_kernel(const float* __restrict__ q,
                                                      const float* __restrict__ p) {
    const int b = blockIdx.x;
    const int t = threadIdx.x;
    const float4* q4 = (const float4*)(q + (size_t)b * D_SZ);
    const float4* p4 = (const float4*)(p + (size_t)b * D_SZ);

    float4 a = q4[t];
    float4 c = p4[t];
    float qq = a.x * a.x + a.y * a.y + a.z * a.z + a.w * a.w;
    float pp = c.x * c.x + c.y * c.y + c.z * c.z + c.w * c.w;
    float qp = a.x * c.x + a.y * c.y + a.z * c.z + a.w * c.w;

    #pragma unroll
    for (int off = 16; off > 0; off >>= 1) {
        qq += __shfl_xor_sync(0xffffffff, qq, off);
        pp += __shfl_xor_sync(0xffffffff, pp, off);
        qp += __shfl_xor_sync(0xffffffff, qp, off);
    }
    __shared__ float sq[8], sp[8], sqp[8], s_rq;
    const int wid = t >> 5, lane = t & 31;
    if (lane == 0) { sq[wid] = qq; sp[wid] = pp; sqp[wid] = qp; }
    __syncthreads();
    if (t == 0) {
        float tq = 0.f, tp = 0.f, tqp = 0.f;
        #pragma unroll
        for (int i = 0; i < 8; i++) { tq += sq[i]; tp += sp[i]; tqp += sqp[i]; }
        float qn = sqrtf(tq), pn = sqrtf(tp);
        float pos = tqp / fmaxf(qn * pn, EPS_F);
        g_s1[b] = __expf(pos * INV_T);
        g_S2[b] = 0.0f;
        s_rq = (qn > 0.f) ? (1.0f / qn) : 0.0f;
    }
    __syncthreads();
    const float rq = s_rq;
    __half* out = g_qhat + (size_t)b * D_SZ + t * 4;
    out[0] = __float2half(a.x * rq);
    out[1] = __float2half(a.y * rq);
    out[2] = __float2half(a.z * rq);
    out[3] = __float2half(a.w * rq);
}

// ---------------------------------------------------------------------------
// Kernel 2: prep negatives -> nhat (fp16)
// ---------------------------------------------------------------------------
__global__ __launch_bounds__(256) void prep_n_kernel(const float* __restrict__ nkeys) {
    const int nrow = blockIdx.x;
    const int t = threadIdx.x;
    const float4* n4 = (const float4*)(nkeys + (size_t)nrow * D_SZ);
    float4 a = n4[t];
    float nn = a.x * a.x + a.y * a.y + a.z * a.z + a.w * a.w;
    #pragma unroll
    for (int off = 16; off > 0; off >>= 1) nn += __shfl_xor_sync(0xffffffff, nn, off);
    __shared__ float sn[8], s_rn;
    const int wid = t >> 5, lane = t & 31;
    if (lane == 0) sn[wid] = nn;
    __syncthreads();
    if (t == 0) {
        float tn = 0.f;
        #pragma unroll
        for (int i = 0; i < 8; i++) tn += sn[i];
        float norm = sqrtf(tn);
        s_rn = (norm > 0.f) ? (1.0f / norm) : 0.0f;
    }
    __syncthreads();
    const float rn = s_rn;
    __half* out = g_nhat + (size_t)nrow * D_SZ + t * 4;
    out[0] = __float2half(a.x * rn);
    out[1] = __float2half(a.y * rn);
    out[2] = __float2half(a.z * rn);
    out[3] = __float2half(a.w * rn);
}

// ---------------------------------------------------------------------------
// Kernel 3: zero loss; keeps GEMM at captured launch slot #4.
// ---------------------------------------------------------------------------
__global__ void init_loss_kernel() {
    if (threadIdx.x == 0) g_loss = 0.0f;
}

// ---------------------------------------------------------------------------
// Kernel 4: wmma GEMM with fp16 ACCUMULATION (tests 2x HMMA rate) + fused
//   exp/rowsum. Block 128(M) x 256(N), 256 threads (8 warps, 2x4), warp tile
//   64x64 (acc = 16 half-frags = 64 regs -> fits 128-reg cap at 2 CTAs/SM).
//   KC=64, 2-stage cp.async, 110.6 KB/CTA -> 2 CTAs/SM.
// ---------------------------------------------------------------------------
#define BM 128
#define BN 256
#define KC 64
#define CHUNKS (D_SZ / KC)        // 16
#define KP 72                     // smem row pitch in fp16 elems (144B)
#define A_ST (BM * KP)            // 9216 elems
#define B_ST (BN * KP)            // 18432 elems
#define STAGE_ELEMS (A_ST + B_ST) // 27648 elems = 55296 B
#define SMEM_BYTES (2 * STAGE_ELEMS * 2)   // 110592
#define CPH 24                    // epilogue scratch pitch (halves)

__global__ __launch_bounds__(256, 2) void gemm_exp_kernel() {
    extern __shared__ __half sm[];
    const int tid = threadIdx.x;
    const int wid = tid >> 5, lane = tid & 31;
    const int wm = wid >> 2;          // 0..1 -> 64-row strip
    const int wn = wid & 3;           // 0..3 -> 64-col strip
    const int m0 = blockIdx.y * BM;
    const int n0 = blockIdx.x * BN;
    const uint32_t sbase = smem_u32(sm);

    // cp.async: rows have 8 16B segs (64 fp16 = 128B).
    //   A: 128*8 = 1024 vecs -> 4/thread.  B: 256*8 = 2048 -> 8/thread.
    uint32_t a_off[4], b_off[8];
    const __half* a_src[4];
    const __half* b_src[8];
    #pragma unroll
    for (int i = 0; i < 4; i++) {
        int idx = tid + i * 256;
        int row = idx >> 3, seg = idx & 7;
        a_off[i] = (uint32_t)(row * KP + seg * 8) * 2;
        a_src[i] = g_qhat + (size_t)(m0 + row) * D_SZ + seg * 8;
    }
    #pragma unroll
    for (int i = 0; i < 8; i++) {
        int idx = tid + i * 256;
        int row = idx >> 3, seg = idx & 7;
        b_off[i] = (uint32_t)(A_ST + row * KP + seg * 8) * 2;
        b_src[i] = g_nhat + (size_t)(n0 + row) * D_SZ + seg * 8;
    }

    wmma::fragment<wmma::accumulator, 16, 16, 16, __half> acc[4][4];
    #pragma unroll
    for (int mf = 0; mf < 4; mf++)
        #pragma unroll
        for (int nf = 0; nf < 4; nf++)
            wmma::fill_fragment(acc[mf][nf], __float2half(0.0f));

    // Prologue: chunk 0 into slot 0
    {
        #pragma unroll
        for (int i = 0; i < 4; i++) CP_ASYNC16(sbase + a_off[i], a_src[i]);
        #pragma unroll
        for (int i = 0; i < 8; i++) CP_ASYNC16(sbase + b_off[i], b_src[i]);
        CP_COMMIT();
    }

    for (int kt = 0; kt < CHUNKS; kt++) {
        if (kt + 1 < CHUNKS) {
            uint32_t st = sbase + ((kt + 1) & 1) * (STAGE_ELEMS * 2);
            int k0 = (kt + 1) * KC;
            #pragma unroll
            for (int i = 0; i < 4; i++) CP_ASYNC16(st + a_off[i], a_src[i] + k0);
            #pragma unroll
            for (int i = 0; i < 8; i++) CP_ASYNC16(st + b_off[i], b_src[i] + k0);
            CP_COMMIT();
            CP_WAIT1();
        } else {
            CP_WAIT0();
        }
        __syncthreads();

        const __half* As = sm + (kt & 1) * STAGE_ELEMS;
        const __half* Bs = As + A_ST;
        #pragma unroll
        for (int kk = 0; kk < 4; kk++) {
            wmma::fragment<wmma::matrix_a, 16, 16, 16, __half, wmma::row_major> af[4];
            #pragma unroll
            for (int mf = 0; mf < 4; mf++)
                wmma::load_matrix_sync(af[mf], As + (wm * 64 + mf * 16) * KP + kk * 16, KP);
            #pragma unroll
            for (int nf = 0; nf < 4; nf++) {
                wmma::fragment<wmma::matrix_b, 16, 16, 16, __half, wmma::col_major> bf;
                wmma::load_matrix_sync(bf, Bs + (wn * 64 + nf * 16) * KP + kk * 16, KP);
                #pragma unroll
                for (int mf = 0; mf < 4; mf++)
                    wmma::mma_sync(acc[mf][nf], af[mf], bf, acc[mf][nf]);
            }
        }
        __syncthreads();   // protect slot (kt&1) before refill at kt+2
    }

    // Epilogue: half accs -> scratch -> exp(fp32) -> rowsum.
    __half* scratch = sm + wid * (16 * CPH);
    #pragma unroll
    for (int mf = 0; mf < 4; mf++) {
        float partial = 0.0f;
        #pragma unroll
        for (int nf = 0; nf < 4; nf++) {
            wmma::store_matrix_sync(scratch, acc[mf][nf], CPH, wmma::mem_row_major);
            __syncwarp();
            const int r = lane & 15, h = lane >> 4;
            const __half* pr = scratch + r * CPH + h * 8;
            #pragma unroll
            for (int c = 0; c < 8; c++)
                partial += __expf(__half2float(pr[c]) * INV_T);
            __syncwarp();
        }
        partial += __shfl_xor_sync(0xffffffff, partial, 16);
        if (lane < 16)
            atomicAdd(&g_S2[m0 + wm * 64 + mf * 16 + lane], partial);
    }
}

// ---------------------------------------------------------------------------
// Kernel 5/6: per-row loss terms -> g_loss; write out.
// ---------------------------------------------------------------------------
__global__ __launch_bounds__(256) void finalize_partial_kernel() {
    const int b = blockIdx.x * 256 + threadIdx.x;
    float s1 = g_s1[b];
    float s2 = g_S2[b] * (1.0f / (float)N_SZ);
    float v = -logf(s1 / (s1 + s2));

    __shared__ float sd[256];
    sd[threadIdx.x] = v;
    __syncthreads();
    #pragma unroll
    for (int stride = 128; stride > 0; stride >>= 1) {
        if (threadIdx.x < stride) sd[threadIdx.x] += sd[threadIdx.x + stride];
        __syncthreads();
    }
    if (threadIdx.x == 0) atomicAdd(&g_loss, sd[0]);
}

__global__ void finalize_write_kernel(float* __restrict__ out) {
    out[0] = g_loss * (1.0f / (float)B_SZ);
}

// ---------------------------------------------------------------------------
extern "C" void kernel_launch(void* const* d_in, const int* in_sizes, int n_in,
                              void* d_out, int out_size) {
    const float* q  = (const float*)d_in[0];
    const float* p  = (const float*)d_in[1];
    const float* nk = (const float*)d_in[2];
    float* out = (float*)d_out;

    cudaFuncSetAttribute(gemm_exp_kernel,
                         cudaFuncAttributeMaxDynamicSharedMemorySize, SMEM_BYTES);

    prep_qp_kernel<<<B_SZ, 256>>>(q, p);
    prep_n_kernel<<<N_SZ, 256>>>(nk);
    init_loss_kernel<<<1, 32>>>();
    gemm_exp_kernel<<<dim3(N_SZ / BN, B_SZ / BM), 256, SMEM_BYTES>>>();
    finalize_partial_kernel<<<B_SZ / 256, 256>>>();
    finalize_write_kernel<<<1, 1>>>(out);
}